// round 4
// baseline (speedup 1.0000x reference)
#include <cuda_runtime.h>
#include <math.h>
#include <stdint.h>

// Problem constants
#define DD   1024          // model dim
#define HH   2048          // expert hidden
#define EE   8             // experts
#define TT   8192          // tokens (B*L = 4*2048)
#define KTOP 2
#define NMOE (TT * KTOP)   // 16384 moe assignments
#define NROWS (NMOE + TT)  // 24576 total grouped rows (moe + shared)

// ---------------------------------------------------------------------------
// Scratch (static __device__ globals: allocation-free per harness rules)
// ---------------------------------------------------------------------------
__device__ float g_hidden[(size_t)NROWS * HH];   // ~192 MiB
__device__ float g_y[(size_t)NMOE * DD];         // ~64 MiB
__device__ int   g_count[EE];
__device__ int   g_offs[EE + 1];
__device__ int   g_tok[EE * TT];                 // per-expert token lists
__device__ int   g_asg_e[NMOE];
__device__ int   g_asg_pos[NMOE];
__device__ float g_asg_w[NMOE];

// ---------------------------------------------------------------------------
// Helpers
// ---------------------------------------------------------------------------
__device__ __forceinline__ uint32_t f2tf(float f) {
    uint32_t r;
    asm("cvt.rna.tf32.f32 %0, %1;" : "=r"(r) : "f"(f));
    return r;
}

__device__ __forceinline__ void mma8(float c[4], const uint32_t a[4], const uint32_t b[2]) {
    asm volatile(
        "mma.sync.aligned.m16n8k8.row.col.f32.tf32.tf32.f32 "
        "{%0,%1,%2,%3},{%4,%5,%6,%7},{%8,%9},{%0,%1,%2,%3};\n"
        : "+f"(c[0]), "+f"(c[1]), "+f"(c[2]), "+f"(c[3])
        : "r"(a[0]), "r"(a[1]), "r"(a[2]), "r"(a[3]), "r"(b[0]), "r"(b[1]));
}

__device__ __forceinline__ float silu_f(float v) {
    return v / (1.0f + __expf(-v));
}

// ---------------------------------------------------------------------------
// K0: zero counts (fresh every graph replay)
// ---------------------------------------------------------------------------
__global__ void zero_counts_kernel() {
    if (threadIdx.x < EE) g_count[threadIdx.x] = 0;
}

// ---------------------------------------------------------------------------
// K1: router — logits, top-2, softmax weights, build expert token lists
// One warp per token. 1024 blocks x 256 threads.
// ---------------------------------------------------------------------------
__global__ void router_kernel(const float* __restrict__ x,
                              const float* __restrict__ rw,
                              const float* __restrict__ bias) {
    int warp = threadIdx.x >> 5;
    int lane = threadIdx.x & 31;
    int t = blockIdx.x * 8 + warp;

    const float* xr = x + (size_t)t * DD;
    float xv[32];
#pragma unroll
    for (int i = 0; i < 32; i++) xv[i] = xr[lane + (i << 5)];

    float logit[EE];
#pragma unroll
    for (int e = 0; e < EE; e++) {
        const float* we = rw + e * DD;
        float acc = 0.0f;
#pragma unroll
        for (int i = 0; i < 32; i++) acc += xv[i] * we[lane + (i << 5)];
#pragma unroll
        for (int o = 16; o > 0; o >>= 1) acc += __shfl_xor_sync(0xffffffffu, acc, o);
        logit[e] = acc + bias[e];
    }

    if (lane == 0) {
        int e0 = 0;
#pragma unroll
        for (int e = 1; e < EE; e++) if (logit[e] > logit[e0]) e0 = e;
        int e1 = -1;
#pragma unroll
        for (int e = 0; e < EE; e++) {
            if (e == e0) continue;
            if (e1 < 0 || logit[e] > logit[e1]) e1 = e;
        }
        float l0 = logit[e0], l1 = logit[e1];
        float p1 = expf(l1 - l0);              // <= 1
        float inv = 1.0f / (1.0f + p1);
        float w0 = inv, w1 = p1 * inv;

        int pos0 = atomicAdd(&g_count[e0], 1);
        int pos1 = atomicAdd(&g_count[e1], 1);
        g_tok[e0 * TT + pos0] = t;
        g_tok[e1 * TT + pos1] = t;
        g_asg_e[2 * t]     = e0; g_asg_pos[2 * t]     = pos0; g_asg_w[2 * t]     = w0;
        g_asg_e[2 * t + 1] = e1; g_asg_pos[2 * t + 1] = pos1; g_asg_w[2 * t + 1] = w1;
    }
}

// ---------------------------------------------------------------------------
// K2: prefix offsets
// ---------------------------------------------------------------------------
__global__ void offsets_kernel() {
    if (threadIdx.x == 0 && blockIdx.x == 0) {
        int a = 0;
        for (int e = 0; e < EE; e++) { g_offs[e] = a; a += g_count[e]; }
        g_offs[EE] = a;   // == 16384
    }
}

// ---------------------------------------------------------------------------
// K3: grouped GEMM1 (dual): hidden = silu(X W1) * (X W3), gathered rows.
// grid (64, HH/64, 9), block 256. Tile 128x64, K-step 16. tf32 mma.
// group z: 0..7 = moe experts (gather via g_tok), 8 = shared (identity).
// ---------------------------------------------------------------------------
__global__ __launch_bounds__(256, 2)
void gemm1_kernel(const float* __restrict__ x,
                  const float* __restrict__ w1, const float* __restrict__ w3,
                  const float* __restrict__ sw1, const float* __restrict__ sw3) {
    int g = blockIdx.z;
    int M, rowbase;
    const int* toks;
    const float *W1, *W3;
    if (g < EE) {
        M = g_count[g]; rowbase = g_offs[g]; toks = g_tok + g * TT;
        W1 = w1 + (size_t)g * DD * HH; W3 = w3 + (size_t)g * DD * HH;
    } else {
        M = TT; rowbase = NMOE; toks = nullptr;
        W1 = sw1; W3 = sw3;
    }
    int bm0 = blockIdx.x * 128;
    if (bm0 >= M) return;
    int n0 = blockIdx.y * 64;

    __shared__ uint32_t As[128 * 20];   // A tile [128][16], row stride 20 (conflict-free)
    __shared__ uint32_t Bs1[16 * 72];   // B tiles [16][64], row stride 72 (conflict-free)
    __shared__ uint32_t Bs3[16 * 72];

    int tid  = threadIdx.x;
    int lane = tid & 31, wid = tid >> 5;
    int wm = wid & 3, wn = wid >> 2;    // 4x2 warps -> 32x32 per warp
    int t4 = lane & 3, t8 = lane >> 2;

    float accG[2][4][4], accU[2][4][4];
#pragma unroll
    for (int mi = 0; mi < 2; mi++)
#pragma unroll
        for (int nj = 0; nj < 4; nj++)
#pragma unroll
            for (int v = 0; v < 4; v++) { accG[mi][nj][v] = 0.0f; accU[mi][nj][v] = 0.0f; }

    // hoist gathered-row pointers (2 float4 A slots per thread)
    const float* arow[2];
    int akq[2], am[2];
#pragma unroll
    for (int i = 0; i < 2; i++) {
        int s = tid + i * 256;          // 0..511 : 128 rows x 4 float4
        int m = s >> 2;
        am[i]  = m;
        akq[i] = (s & 3) << 2;
        int gm = bm0 + m;
        if (gm < M) {
            int trow = toks ? toks[gm] : gm;
            arow[i] = x + (size_t)trow * DD;
        } else {
            arow[i] = nullptr;
        }
    }
    // B slot per thread
    int bk  = tid >> 4;                 // 0..15
    int bnq = (tid & 15) << 2;          // 0..60

    for (int kb = 0; kb < DD / 16; kb++) {
        int k0 = kb * 16;
#pragma unroll
        for (int i = 0; i < 2; i++) {
            float4 v = make_float4(0.f, 0.f, 0.f, 0.f);
            if (arow[i]) v = *reinterpret_cast<const float4*>(arow[i] + k0 + akq[i]);
            uint32_t* dst = &As[am[i] * 20 + akq[i]];
            dst[0] = f2tf(v.x); dst[1] = f2tf(v.y); dst[2] = f2tf(v.z); dst[3] = f2tf(v.w);
        }
        {
            const float4 b1v = *reinterpret_cast<const float4*>(W1 + (size_t)(k0 + bk) * HH + n0 + bnq);
            const float4 b3v = *reinterpret_cast<const float4*>(W3 + (size_t)(k0 + bk) * HH + n0 + bnq);
            uint32_t* d1 = &Bs1[bk * 72 + bnq];
            d1[0] = f2tf(b1v.x); d1[1] = f2tf(b1v.y); d1[2] = f2tf(b1v.z); d1[3] = f2tf(b1v.w);
            uint32_t* d3 = &Bs3[bk * 72 + bnq];
            d3[0] = f2tf(b3v.x); d3[1] = f2tf(b3v.y); d3[2] = f2tf(b3v.z); d3[3] = f2tf(b3v.w);
        }
        __syncthreads();

#pragma unroll
        for (int ks = 0; ks < 2; ks++) {
            int kk = ks * 8;
            uint32_t a[2][4];
#pragma unroll
            for (int mi = 0; mi < 2; mi++) {
                int mr = wm * 32 + mi * 16 + t8;
                a[mi][0] = As[mr * 20 + kk + t4];
                a[mi][1] = As[(mr + 8) * 20 + kk + t4];
                a[mi][2] = As[mr * 20 + kk + t4 + 4];
                a[mi][3] = As[(mr + 8) * 20 + kk + t4 + 4];
            }
            uint32_t b1r[4][2], b3r[4][2];
#pragma unroll
            for (int nj = 0; nj < 4; nj++) {
                int nc = wn * 32 + nj * 8 + t8;
                b1r[nj][0] = Bs1[(kk + t4) * 72 + nc];
                b1r[nj][1] = Bs1[(kk + t4 + 4) * 72 + nc];
                b3r[nj][0] = Bs3[(kk + t4) * 72 + nc];
                b3r[nj][1] = Bs3[(kk + t4 + 4) * 72 + nc];
            }
#pragma unroll
            for (int mi = 0; mi < 2; mi++)
#pragma unroll
                for (int nj = 0; nj < 4; nj++) {
                    mma8(accG[mi][nj], a[mi], b1r[nj]);
                    mma8(accU[mi][nj], a[mi], b3r[nj]);
                }
        }
        __syncthreads();
    }

    // epilogue: silu(G) * U -> g_hidden
#pragma unroll
    for (int mi = 0; mi < 2; mi++) {
#pragma unroll
        for (int h = 0; h < 2; h++) {
            int row = wm * 32 + mi * 16 + t8 + h * 8;
            int grow = bm0 + row;
            if (grow < M) {
                size_t base = (size_t)(rowbase + grow) * HH + n0;
#pragma unroll
                for (int nj = 0; nj < 4; nj++) {
                    int col = wn * 32 + nj * 8 + t4 * 2;
                    float gg0 = accG[mi][nj][h * 2 + 0];
                    float gg1 = accG[mi][nj][h * 2 + 1];
                    float uu0 = accU[mi][nj][h * 2 + 0];
                    float uu1 = accU[mi][nj][h * 2 + 1];
                    float2 st;
                    st.x = silu_f(gg0) * uu0;
                    st.y = silu_f(gg1) * uu1;
                    *reinterpret_cast<float2*>(&g_hidden[base + col]) = st;
                }
            }
        }
    }
}

// ---------------------------------------------------------------------------
// K4: grouped GEMM2: y = hidden @ W2  (moe -> g_y, shared -> out directly)
// grid (64, DD/64, 9), block 256. K-dim = HH (128 iters).
// ---------------------------------------------------------------------------
__global__ __launch_bounds__(256, 2)
void gemm2_kernel(const float* __restrict__ w2, const float* __restrict__ sw2,
                  float* __restrict__ out) {
    int g = blockIdx.z;
    int M, rowbase;
    const float* W;
    if (g < EE) {
        M = g_count[g]; rowbase = g_offs[g];
        W = w2 + (size_t)g * HH * DD;
    } else {
        M = TT; rowbase = NMOE; W = sw2;
    }
    int bm0 = blockIdx.x * 128;
    if (bm0 >= M) return;
    int n0 = blockIdx.y * 64;

    __shared__ uint32_t As[128 * 20];
    __shared__ uint32_t Bs[16 * 72];

    int tid  = threadIdx.x;
    int lane = tid & 31, wid = tid >> 5;
    int wm = wid & 3, wn = wid >> 2;
    int t4 = lane & 3, t8 = lane >> 2;

    float acc[2][4][4];
#pragma unroll
    for (int mi = 0; mi < 2; mi++)
#pragma unroll
        for (int nj = 0; nj < 4; nj++)
#pragma unroll
            for (int v = 0; v < 4; v++) acc[mi][nj][v] = 0.0f;

    const float* arow[2];
    int akq[2], am[2];
#pragma unroll
    for (int i = 0; i < 2; i++) {
        int s = tid + i * 256;
        int m = s >> 2;
        am[i]  = m;
        akq[i] = (s & 3) << 2;
        int gm = bm0 + m;
        arow[i] = (gm < M) ? (g_hidden + (size_t)(rowbase + gm) * HH) : nullptr;
    }
    int bk  = tid >> 4;
    int bnq = (tid & 15) << 2;

    for (int kb = 0; kb < HH / 16; kb++) {
        int k0 = kb * 16;
#pragma unroll
        for (int i = 0; i < 2; i++) {
            float4 v = make_float4(0.f, 0.f, 0.f, 0.f);
            if (arow[i]) v = *reinterpret_cast<const float4*>(arow[i] + k0 + akq[i]);
            uint32_t* dst = &As[am[i] * 20 + akq[i]];
            dst[0] = f2tf(v.x); dst[1] = f2tf(v.y); dst[2] = f2tf(v.z); dst[3] = f2tf(v.w);
        }
        {
            const float4 bv = *reinterpret_cast<const float4*>(W + (size_t)(k0 + bk) * DD + n0 + bnq);
            uint32_t* d = &Bs[bk * 72 + bnq];
            d[0] = f2tf(bv.x); d[1] = f2tf(bv.y); d[2] = f2tf(bv.z); d[3] = f2tf(bv.w);
        }
        __syncthreads();

#pragma unroll
        for (int ks = 0; ks < 2; ks++) {
            int kk = ks * 8;
            uint32_t a[2][4];
#pragma unroll
            for (int mi = 0; mi < 2; mi++) {
                int mr = wm * 32 + mi * 16 + t8;
                a[mi][0] = As[mr * 20 + kk + t4];
                a[mi][1] = As[(mr + 8) * 20 + kk + t4];
                a[mi][2] = As[mr * 20 + kk + t4 + 4];
                a[mi][3] = As[(mr + 8) * 20 + kk + t4 + 4];
            }
            uint32_t br[4][2];
#pragma unroll
            for (int nj = 0; nj < 4; nj++) {
                int nc = wn * 32 + nj * 8 + t8;
                br[nj][0] = Bs[(kk + t4) * 72 + nc];
                br[nj][1] = Bs[(kk + t4 + 4) * 72 + nc];
            }
#pragma unroll
            for (int mi = 0; mi < 2; mi++)
#pragma unroll
                for (int nj = 0; nj < 4; nj++)
                    mma8(acc[mi][nj], a[mi], br[nj]);
        }
        __syncthreads();
    }

#pragma unroll
    for (int mi = 0; mi < 2; mi++) {
#pragma unroll
        for (int h = 0; h < 2; h++) {
            int row = wm * 32 + mi * 16 + t8 + h * 8;
            int grow = bm0 + row;
            if (grow < M) {
#pragma unroll
                for (int nj = 0; nj < 4; nj++) {
                    int col = wn * 32 + nj * 8 + t4 * 2;
                    float2 st;
                    st.x = acc[mi][nj][h * 2 + 0];
                    st.y = acc[mi][nj][h * 2 + 1];
                    if (g < EE) {
                        size_t base = (size_t)(rowbase + grow) * DD + n0;
                        *reinterpret_cast<float2*>(&g_y[base + col]) = st;
                    } else {
                        size_t base = (size_t)grow * DD + n0;   // grow == token id
                        *reinterpret_cast<float2*>(&out[base + col]) = st;
                    }
                }
            }
        }
    }
}

// ---------------------------------------------------------------------------
// K5: combine: out[t] += w0*y[r0] + w1*y[r1]   (deterministic, no atomics)
// ---------------------------------------------------------------------------
__global__ void combine_kernel(float* __restrict__ out) {
    int t = blockIdx.x;
    int e0 = g_asg_e[2 * t],     e1 = g_asg_e[2 * t + 1];
    int r0 = g_offs[e0] + g_asg_pos[2 * t];
    int r1 = g_offs[e1] + g_asg_pos[2 * t + 1];
    float w0 = g_asg_w[2 * t], w1 = g_asg_w[2 * t + 1];

    int c = threadIdx.x * 4;
    float4 o  = *reinterpret_cast<const float4*>(out + (size_t)t * DD + c);
    float4 y0 = *reinterpret_cast<const float4*>(g_y + (size_t)r0 * DD + c);
    float4 y1 = *reinterpret_cast<const float4*>(g_y + (size_t)r1 * DD + c);
    o.x += w0 * y0.x + w1 * y1.x;
    o.y += w0 * y0.y + w1 * y1.y;
    o.z += w0 * y0.z + w1 * y1.z;
    o.w += w0 * y0.w + w1 * y1.w;
    *reinterpret_cast<float4*>(out + (size_t)t * DD + c) = o;
}

// ---------------------------------------------------------------------------
// Launch
// ---------------------------------------------------------------------------
extern "C" void kernel_launch(void* const* d_in, const int* in_sizes, int n_in,
                              void* d_out, int out_size) {
    const float* x    = (const float*)d_in[0];
    const float* rw   = (const float*)d_in[1];
    const float* bias = (const float*)d_in[2];
    const float* w1   = (const float*)d_in[3];
    const float* w3   = (const float*)d_in[4];
    const float* w2   = (const float*)d_in[5];
    const float* sw1  = (const float*)d_in[6];
    const float* sw3  = (const float*)d_in[7];
    const float* sw2  = (const float*)d_in[8];
    float* out = (float*)d_out;

    zero_counts_kernel<<<1, 32>>>();
    router_kernel<<<TT / 8, 256>>>(x, rw, bias);
    offsets_kernel<<<1, 32>>>();

    dim3 grid1(TT / 128, HH / 64, EE + 1);
    gemm1_kernel<<<grid1, 256>>>(x, w1, w3, sw1, sw3);

    dim3 grid2(TT / 128, DD / 64, EE + 1);
    gemm2_kernel<<<grid2, 256>>>(w2, sw2, out);

    combine_kernel<<<TT, 256>>>(out);
}

// round 6
// speedup vs baseline: 1.4013x; 1.4013x over previous
#include <cuda_runtime.h>
#include <math.h>
#include <stdint.h>

// Problem constants
#define DD   1024          // model dim
#define HH   2048          // expert hidden
#define EE   8             // experts
#define TT   8192          // tokens (B*L = 4*2048)
#define KTOP 2
#define NMOE (TT * KTOP)   // 16384 moe assignments
#define NROWS (NMOE + TT)  // 24576 total grouped rows (moe + shared)

// ---------------------------------------------------------------------------
// Scratch (static __device__ globals: allocation-free per harness rules)
// ---------------------------------------------------------------------------
__device__ float g_hidden[(size_t)NROWS * HH];   // ~192 MiB
__device__ float g_y[(size_t)NMOE * DD];         // ~64 MiB
__device__ int   g_count[EE];
__device__ int   g_offs[EE + 1];
__device__ int   g_tok[EE * TT];                 // per-expert token lists
__device__ int   g_asg_e[NMOE];
__device__ int   g_asg_pos[NMOE];
__device__ float g_asg_w[NMOE];

// ---------------------------------------------------------------------------
// Helpers
// ---------------------------------------------------------------------------
__device__ __forceinline__ uint32_t f2tf(float f) {
    uint32_t r;
    asm("cvt.rna.tf32.f32 %0, %1;" : "=r"(r) : "f"(f));
    return r;
}
__device__ __forceinline__ uint32_t tfbits(uint32_t raw) {
    return f2tf(__uint_as_float(raw));
}

__device__ __forceinline__ void mma8(float c[4], const uint32_t a[4], const uint32_t b[2]) {
    asm volatile(
        "mma.sync.aligned.m16n8k8.row.col.f32.tf32.tf32.f32 "
        "{%0,%1,%2,%3},{%4,%5,%6,%7},{%8,%9},{%0,%1,%2,%3};\n"
        : "+f"(c[0]), "+f"(c[1]), "+f"(c[2]), "+f"(c[3])
        : "r"(a[0]), "r"(a[1]), "r"(a[2]), "r"(a[3]), "r"(b[0]), "r"(b[1]));
}

__device__ __forceinline__ void cp16(uint32_t smem_dst, const void* gmem_src, int src_size) {
    asm volatile("cp.async.ca.shared.global [%0], [%1], 16, %2;"
                 :: "r"(smem_dst), "l"(gmem_src), "r"(src_size));
}
__device__ __forceinline__ void cp_commit() { asm volatile("cp.async.commit_group;"); }
__device__ __forceinline__ void cp_wait1()  { asm volatile("cp.async.wait_group 1;" ::: "memory"); }

__device__ __forceinline__ float silu_f(float v) {
    return v / (1.0f + __expf(-v));
}

// ---------------------------------------------------------------------------
// K0: zero counts (fresh every graph replay)
// ---------------------------------------------------------------------------
__global__ void zero_counts_kernel() {
    if (threadIdx.x < EE) g_count[threadIdx.x] = 0;
}

// ---------------------------------------------------------------------------
// K1: router — logits, top-2, softmax weights, build expert token lists
// ---------------------------------------------------------------------------
__global__ void router_kernel(const float* __restrict__ x,
                              const float* __restrict__ rw,
                              const float* __restrict__ bias) {
    int warp = threadIdx.x >> 5;
    int lane = threadIdx.x & 31;
    int t = blockIdx.x * 8 + warp;

    const float* xr = x + (size_t)t * DD;
    float xv[32];
#pragma unroll
    for (int i = 0; i < 32; i++) xv[i] = xr[lane + (i << 5)];

    float logit[EE];
#pragma unroll
    for (int e = 0; e < EE; e++) {
        const float* we = rw + e * DD;
        float acc = 0.0f;
#pragma unroll
        for (int i = 0; i < 32; i++) acc += xv[i] * we[lane + (i << 5)];
#pragma unroll
        for (int o = 16; o > 0; o >>= 1) acc += __shfl_xor_sync(0xffffffffu, acc, o);
        logit[e] = acc + bias[e];
    }

    if (lane == 0) {
        int e0 = 0;
#pragma unroll
        for (int e = 1; e < EE; e++) if (logit[e] > logit[e0]) e0 = e;
        int e1 = -1;
#pragma unroll
        for (int e = 0; e < EE; e++) {
            if (e == e0) continue;
            if (e1 < 0 || logit[e] > logit[e1]) e1 = e;
        }
        float l0 = logit[e0], l1 = logit[e1];
        float p1 = expf(l1 - l0);              // <= 1
        float inv = 1.0f / (1.0f + p1);
        float w0 = inv, w1 = p1 * inv;

        int pos0 = atomicAdd(&g_count[e0], 1);
        int pos1 = atomicAdd(&g_count[e1], 1);
        g_tok[e0 * TT + pos0] = t;
        g_tok[e1 * TT + pos1] = t;
        g_asg_e[2 * t]     = e0; g_asg_pos[2 * t]     = pos0; g_asg_w[2 * t]     = w0;
        g_asg_e[2 * t + 1] = e1; g_asg_pos[2 * t + 1] = pos1; g_asg_w[2 * t + 1] = w1;
    }
}

// ---------------------------------------------------------------------------
// K2: prefix offsets
// ---------------------------------------------------------------------------
__global__ void offsets_kernel() {
    if (threadIdx.x == 0 && blockIdx.x == 0) {
        int a = 0;
        for (int e = 0; e < EE; e++) { g_offs[e] = a; a += g_count[e]; }
        g_offs[EE] = a;
    }
}

// ---------------------------------------------------------------------------
// K3: grouped GEMM1 (dual): hidden = silu(X W1) * (X W3), gathered rows.
// grid (64, HH/64, 9), block 256. Tile 128x64 dual. 2-stage cp.async pipeline.
// ---------------------------------------------------------------------------
#define A_WORDS (128 * 20)
#define B1_WORDS (16 * 72)

__global__ __launch_bounds__(256, 2)
void gemm1_kernel(const float* __restrict__ x,
                  const float* __restrict__ w1, const float* __restrict__ w3,
                  const float* __restrict__ sw1, const float* __restrict__ sw3) {
    int g = blockIdx.z;
    int M, rowbase;
    const int* toks;
    const float *W1, *W3;
    if (g < EE) {
        M = g_count[g]; rowbase = g_offs[g]; toks = g_tok + g * TT;
        W1 = w1 + (size_t)g * DD * HH; W3 = w3 + (size_t)g * DD * HH;
    } else {
        M = TT; rowbase = NMOE; toks = nullptr;
        W1 = sw1; W3 = sw3;
    }
    int bm0 = blockIdx.x * 128;
    if (bm0 >= M) return;
    int n0 = blockIdx.y * 64;

    __shared__ uint32_t As[2][A_WORDS];    // raw fp32 bits, stride 20 (conflict-free)
    __shared__ uint32_t Bs1[2][B1_WORDS];  // stride 72 (conflict-free)
    __shared__ uint32_t Bs3[2][B1_WORDS];

    int tid  = threadIdx.x;
    int lane = tid & 31, wid = tid >> 5;
    int wm = wid & 3, wn = wid >> 2;       // 4x2 warps -> 32x32 per warp
    int t4 = lane & 3, t8 = lane >> 2;

    float accG[2][4][4] = {}, accU[2][4][4] = {};

    // A prefetch slots: 2 x 16B per thread (128 rows x 4 chunks)
    const float* arow[2];
    int asz[2];
    uint32_t adst[2];
#pragma unroll
    for (int i = 0; i < 2; i++) {
        int s = tid + i * 256;
        int m = s >> 2;
        int kq = (s & 3) << 2;
        int gm = bm0 + m;
        if (gm < M) {
            int tr = toks ? toks[gm] : gm;
            arow[i] = x + (size_t)tr * DD + kq;
            asz[i] = 16;
        } else {
            arow[i] = x;   // unused (src_size 0 -> zero fill)
            asz[i] = 0;
        }
        adst[i] = (uint32_t)__cvta_generic_to_shared(&As[0][m * 20 + kq]);
    }
    // B slot: 1 x 16B per matrix per thread (16 rows x 16 chunks)
    int bk  = tid >> 4;
    int bnq = (tid & 15) << 2;
    const float* b1src = W1 + (size_t)bk * HH + n0 + bnq;
    const float* b3src = W3 + (size_t)bk * HH + n0 + bnq;
    uint32_t b1dst = (uint32_t)__cvta_generic_to_shared(&Bs1[0][bk * 72 + bnq]);
    uint32_t b3dst = (uint32_t)__cvta_generic_to_shared(&Bs3[0][bk * 72 + bnq]);

    const uint32_t A_STG = A_WORDS * 4, B_STG = B1_WORDS * 4;

    // prologue: prefetch tile 0
    {
        cp16(adst[0], arow[0], asz[0]);
        cp16(adst[1], arow[1], asz[1]);
        cp16(b1dst, b1src, 16);
        cp16(b3dst, b3src, 16);
        cp_commit();
    }

    const int KB = DD / 16;
    for (int kb = 0; kb < KB; kb++) {
        int buf = kb & 1;
        if (kb + 1 < KB) {
            int nb = buf ^ 1;
            int k0 = (kb + 1) * 16;
            cp16(adst[0] + nb * A_STG, arow[0] + k0, asz[0]);
            cp16(adst[1] + nb * A_STG, arow[1] + k0, asz[1]);
            cp16(b1dst + nb * B_STG, b1src + (size_t)k0 * HH, 16);
            cp16(b3dst + nb * B_STG, b3src + (size_t)k0 * HH, 16);
        }
        cp_commit();
        cp_wait1();
        __syncthreads();

        const uint32_t* A_  = As[buf];
        const uint32_t* B1_ = Bs1[buf];
        const uint32_t* B3_ = Bs3[buf];

#pragma unroll
        for (int ks = 0; ks < 2; ks++) {
            int kk = ks * 8;
            uint32_t a[2][4];
#pragma unroll
            for (int mi = 0; mi < 2; mi++) {
                int mr = wm * 32 + mi * 16 + t8;
                a[mi][0] = tfbits(A_[mr * 20 + kk + t4]);
                a[mi][1] = tfbits(A_[(mr + 8) * 20 + kk + t4]);
                a[mi][2] = tfbits(A_[mr * 20 + kk + t4 + 4]);
                a[mi][3] = tfbits(A_[(mr + 8) * 20 + kk + t4 + 4]);
            }
            uint32_t b1r[4][2], b3r[4][2];
#pragma unroll
            for (int nj = 0; nj < 4; nj++) {
                int nc = wn * 32 + nj * 8 + t8;
                b1r[nj][0] = tfbits(B1_[(kk + t4) * 72 + nc]);
                b1r[nj][1] = tfbits(B1_[(kk + t4 + 4) * 72 + nc]);
                b3r[nj][0] = tfbits(B3_[(kk + t4) * 72 + nc]);
                b3r[nj][1] = tfbits(B3_[(kk + t4 + 4) * 72 + nc]);
            }
#pragma unroll
            for (int mi = 0; mi < 2; mi++)
#pragma unroll
                for (int nj = 0; nj < 4; nj++) {
                    mma8(accG[mi][nj], a[mi], b1r[nj]);
                    mma8(accU[mi][nj], a[mi], b3r[nj]);
                }
        }
        __syncthreads();   // protect buf before it is overwritten by next prefetch
    }

    // epilogue: silu(G) * U -> g_hidden
#pragma unroll
    for (int mi = 0; mi < 2; mi++) {
#pragma unroll
        for (int h = 0; h < 2; h++) {
            int row = wm * 32 + mi * 16 + t8 + h * 8;
            int grow = bm0 + row;
            if (grow < M) {
                size_t base = (size_t)(rowbase + grow) * HH + n0;
#pragma unroll
                for (int nj = 0; nj < 4; nj++) {
                    int col = wn * 32 + nj * 8 + t4 * 2;
                    float2 st;
                    st.x = silu_f(accG[mi][nj][h * 2 + 0]) * accU[mi][nj][h * 2 + 0];
                    st.y = silu_f(accG[mi][nj][h * 2 + 1]) * accU[mi][nj][h * 2 + 1];
                    *reinterpret_cast<float2*>(&g_hidden[base + col]) = st;
                }
            }
        }
    }
}

// ---------------------------------------------------------------------------
// K4: grouped GEMM2: y = hidden @ W2  (moe -> g_y, shared -> out directly)
// grid (64, DD/128, 9), block 256. Tile 128x128. 2-stage cp.async pipeline.
// ---------------------------------------------------------------------------
#define B2_WORDS (16 * 136)

__global__ __launch_bounds__(256, 2)
void gemm2_kernel(const float* __restrict__ w2, const float* __restrict__ sw2,
                  float* __restrict__ out) {
    int g = blockIdx.z;
    int M, rowbase;
    const float* W;
    if (g < EE) {
        M = g_count[g]; rowbase = g_offs[g];
        W = w2 + (size_t)g * HH * DD;
    } else {
        M = TT; rowbase = NMOE; W = sw2;
    }
    int bm0 = blockIdx.x * 128;
    if (bm0 >= M) return;
    int n0 = blockIdx.y * 128;

    __shared__ uint32_t As[2][A_WORDS];    // stride 20
    __shared__ uint32_t Bs[2][B2_WORDS];   // 16 x 128, stride 136 (136%32==8 -> conflict-free)

    int tid  = threadIdx.x;
    int lane = tid & 31, wid = tid >> 5;
    int wm = wid & 3, wn = wid >> 2;       // warp tile 32 x 64
    int t4 = lane & 3, t8 = lane >> 2;

    float acc[2][8][4] = {};

    const float* arow[2];
    int asz[2];
    uint32_t adst[2];
#pragma unroll
    for (int i = 0; i < 2; i++) {
        int s = tid + i * 256;
        int m = s >> 2;
        int kq = (s & 3) << 2;
        int gm = bm0 + m;
        if (gm < M) {
            arow[i] = g_hidden + (size_t)(rowbase + gm) * HH + kq;
            asz[i] = 16;
        } else {
            arow[i] = g_hidden;
            asz[i] = 0;
        }
        adst[i] = (uint32_t)__cvta_generic_to_shared(&As[0][m * 20 + kq]);
    }
    // B: 16 rows x 128 floats = 512 chunks of 16B -> 2 per thread
    const float* bsrc[2];
    uint32_t bdst[2];
#pragma unroll
    for (int i = 0; i < 2; i++) {
        int s = tid + i * 256;
        int k = s >> 5;
        int nq = (s & 31) << 2;
        bsrc[i] = W + (size_t)k * DD + n0 + nq;
        bdst[i] = (uint32_t)__cvta_generic_to_shared(&Bs[0][k * 136 + nq]);
    }

    const uint32_t A_STG = A_WORDS * 4, B_STG = B2_WORDS * 4;

    {
        cp16(adst[0], arow[0], asz[0]);
        cp16(adst[1], arow[1], asz[1]);
        cp16(bdst[0], bsrc[0], 16);
        cp16(bdst[1], bsrc[1], 16);
        cp_commit();
    }

    const int KB = HH / 16;
    for (int kb = 0; kb < KB; kb++) {
        int buf = kb & 1;
        if (kb + 1 < KB) {
            int nb = buf ^ 1;
            int k0 = (kb + 1) * 16;
            cp16(adst[0] + nb * A_STG, arow[0] + k0, asz[0]);
            cp16(adst[1] + nb * A_STG, arow[1] + k0, asz[1]);
            cp16(bdst[0] + nb * B_STG, bsrc[0] + (size_t)k0 * DD, 16);
            cp16(bdst[1] + nb * B_STG, bsrc[1] + (size_t)k0 * DD, 16);
        }
        cp_commit();
        cp_wait1();
        __syncthreads();

        const uint32_t* A_ = As[buf];
        const uint32_t* B_ = Bs[buf];

#pragma unroll
        for (int ks = 0; ks < 2; ks++) {
            int kk = ks * 8;
            uint32_t a[2][4];
#pragma unroll
            for (int mi = 0; mi < 2; mi++) {
                int mr = wm * 32 + mi * 16 + t8;
                a[mi][0] = tfbits(A_[mr * 20 + kk + t4]);
                a[mi][1] = tfbits(A_[(mr + 8) * 20 + kk + t4]);
                a[mi][2] = tfbits(A_[mr * 20 + kk + t4 + 4]);
                a[mi][3] = tfbits(A_[(mr + 8) * 20 + kk + t4 + 4]);
            }
            uint32_t br[8][2];
#pragma unroll
            for (int nj = 0; nj < 8; nj++) {
                int nc = wn * 64 + nj * 8 + t8;
                br[nj][0] = tfbits(B_[(kk + t4) * 136 + nc]);
                br[nj][1] = tfbits(B_[(kk + t4 + 4) * 136 + nc]);
            }
#pragma unroll
            for (int mi = 0; mi < 2; mi++)
#pragma unroll
                for (int nj = 0; nj < 8; nj++)
                    mma8(acc[mi][nj], a[mi], br[nj]);
        }
        __syncthreads();
    }

#pragma unroll
    for (int mi = 0; mi < 2; mi++) {
#pragma unroll
        for (int h = 0; h < 2; h++) {
            int row = wm * 32 + mi * 16 + t8 + h * 8;
            int grow = bm0 + row;
            if (grow < M) {
#pragma unroll
                for (int nj = 0; nj < 8; nj++) {
                    int col = wn * 64 + nj * 8 + t4 * 2;
                    float2 st;
                    st.x = acc[mi][nj][h * 2 + 0];
                    st.y = acc[mi][nj][h * 2 + 1];
                    if (g < EE) {
                        size_t base = (size_t)(rowbase + grow) * DD + n0;
                        *reinterpret_cast<float2*>(&g_y[base + col]) = st;
                    } else {
                        size_t base = (size_t)grow * DD + n0;   // grow == token id
                        *reinterpret_cast<float2*>(&out[base + col]) = st;
                    }
                }
            }
        }
    }
}

// ---------------------------------------------------------------------------
// K5: combine: out[t] += w0*y[r0] + w1*y[r1]   (deterministic, no atomics)
// ---------------------------------------------------------------------------
__global__ void combine_kernel(float* __restrict__ out) {
    int t = blockIdx.x;
    int e0 = g_asg_e[2 * t],     e1 = g_asg_e[2 * t + 1];
    int r0 = g_offs[e0] + g_asg_pos[2 * t];
    int r1 = g_offs[e1] + g_asg_pos[2 * t + 1];
    float w0 = g_asg_w[2 * t], w1 = g_asg_w[2 * t + 1];

    int c = threadIdx.x * 4;
    float4 o  = *reinterpret_cast<const float4*>(out + (size_t)t * DD + c);
    float4 y0 = *reinterpret_cast<const float4*>(g_y + (size_t)r0 * DD + c);
    float4 y1 = *reinterpret_cast<const float4*>(g_y + (size_t)r1 * DD + c);
    o.x += w0 * y0.x + w1 * y1.x;
    o.y += w0 * y0.y + w1 * y1.y;
    o.z += w0 * y0.z + w1 * y1.z;
    o.w += w0 * y0.w + w1 * y1.w;
    *reinterpret_cast<float4*>(out + (size_t)t * DD + c) = o;
}

// ---------------------------------------------------------------------------
// Launch
// ---------------------------------------------------------------------------
extern "C" void kernel_launch(void* const* d_in, const int* in_sizes, int n_in,
                              void* d_out, int out_size) {
    const float* x    = (const float*)d_in[0];
    const float* rw   = (const float*)d_in[1];
    const float* bias = (const float*)d_in[2];
    const float* w1   = (const float*)d_in[3];
    const float* w3   = (const float*)d_in[4];
    const float* w2   = (const float*)d_in[5];
    const float* sw1  = (const float*)d_in[6];
    const float* sw3  = (const float*)d_in[7];
    const float* sw2  = (const float*)d_in[8];
    float* out = (float*)d_out;

    zero_counts_kernel<<<1, 32>>>();
    router_kernel<<<TT / 8, 256>>>(x, rw, bias);
    offsets_kernel<<<1, 32>>>();

    dim3 grid1(TT / 128, HH / 64, EE + 1);
    gemm1_kernel<<<grid1, 256>>>(x, w1, w3, sw1, sw3);

    dim3 grid2(TT / 128, DD / 128, EE + 1);
    gemm2_kernel<<<grid2, 256>>>(w2, sw2, out);

    combine_kernel<<<TT, 256>>>(out);
}